// round 14
// baseline (speedup 1.0000x reference)
#include <cuda_runtime.h>
#include <cuda_fp16.h>
#include <stdint.h>

#define NB 16
#define NC 512
#define NS 32
#define NH 8
#define ND 64
#define NSEQ 1024
#define LOG2E 1.44269504f

// ---------------- scratch ----------------
__device__ __align__(16) __half g_xn[(size_t)NB * NC * NSEQ];       // LN-normalized x, fp16
__device__ __align__(16) __half g_w16qkv[3 * NC * NC];              // fp16 weights
__device__ __align__(16) __half g_w16out[NC * NC];
__device__ __align__(16) __half g_qkv[(size_t)NB * 3 * NC * NSEQ];  // [B,1536,1024] fp16
__device__ __align__(16) __half g_q[(size_t)NB * NH * NSEQ * ND];   // [bh,seq,d] fp16
__device__ __align__(16) __half g_k[(size_t)NB * NH * NSEQ * ND];
__device__ __align__(16) __half g_v[(size_t)NB * NH * NSEQ * ND];
__device__ __align__(16) __half g_att[(size_t)NB * NC * NSEQ];      // [B,512,1024] fp16

__device__ __forceinline__ float ex2(float x) {
    float r; asm("ex2.approx.ftz.f32 %0, %1;" : "=f"(r) : "f"(x)); return r;
}
__device__ __forceinline__ uint32_t smem_u32(const void* p) {
    uint32_t a;
    asm("{ .reg .u64 t; cvta.to.shared.u64 t, %1; cvt.u32.u64 %0, t; }" : "=r"(a) : "l"(p));
    return a;
}
__device__ __forceinline__ void mma_f16(float* c, const uint32_t* a, uint32_t b0, uint32_t b1) {
    asm volatile(
        "mma.sync.aligned.m16n8k16.row.col.f32.f16.f16.f32 "
        "{%0,%1,%2,%3}, {%4,%5,%6,%7}, {%8,%9}, {%0,%1,%2,%3};"
        : "+f"(c[0]), "+f"(c[1]), "+f"(c[2]), "+f"(c[3])
        : "r"(a[0]), "r"(a[1]), "r"(a[2]), "r"(a[3]), "r"(b0), "r"(b1));
}
__device__ __forceinline__ void ldsm4(uint32_t& r0, uint32_t& r1, uint32_t& r2, uint32_t& r3,
                                      uint32_t addr) {
    asm volatile("ldmatrix.sync.aligned.m8n8.x4.shared.b16 {%0,%1,%2,%3}, [%4];"
                 : "=r"(r0), "=r"(r1), "=r"(r2), "=r"(r3) : "r"(addr));
}
__device__ __forceinline__ void ldsm4t(uint32_t& r0, uint32_t& r1, uint32_t& r2, uint32_t& r3,
                                       uint32_t addr) {
    asm volatile("ldmatrix.sync.aligned.m8n8.x4.trans.shared.b16 {%0,%1,%2,%3}, [%4];"
                 : "=r"(r0), "=r"(r1), "=r"(r2), "=r"(r3) : "r"(addr));
}
#define CP16(dst, src) asm volatile("cp.async.cg.shared.global [%0], [%1], 16;" :: "r"(dst), "l"(src))
#define CPCOMMIT() asm volatile("cp.async.commit_group;" ::)
#define CPWAIT(n) asm volatile("cp.async.wait_group %0;" :: "n"(n))

// ---------------- 0) weight fp32 -> fp16 ----------------
__global__ __launch_bounds__(256) void wconv_kernel(const float* __restrict__ wq,
                                                    const float* __restrict__ wo,
                                                    __half* __restrict__ hq,
                                                    __half* __restrict__ ho)
{
    int idx = blockIdx.x * 256 + threadIdx.x;
    const int n1 = 3 * NC * NC / 4;
    if (idx < n1) {
        float4 v = *(const float4*)(wq + (size_t)idx * 4);
        *(half2*)(hq + (size_t)idx * 4)     = __floats2half2_rn(v.x, v.y);
        *(half2*)(hq + (size_t)idx * 4 + 2) = __floats2half2_rn(v.z, v.w);
    } else {
        int j = idx - n1;
        float4 v = *(const float4*)(wo + (size_t)j * 4);
        *(half2*)(ho + (size_t)j * 4)     = __floats2half2_rn(v.x, v.y);
        *(half2*)(ho + (size_t)j * 4 + 2) = __floats2half2_rn(v.z, v.w);
    }
}

// ---------------- 1) fused stats + LN-normalize -> fp16 xn ----------------
__global__ __launch_bounds__(256) void stats_norm_kernel(const float* __restrict__ x,
                                                         const float* __restrict__ scale,
                                                         __half* __restrict__ xn)
{
    __shared__ float ssum[8][33], ssq[8][33];
    __shared__ float smn[32], srs[32];
    int bid = blockIdx.x;
    int b = bid >> 5, pg = (bid & 31) * 32;
    int tid = threadIdx.x;
    int px = tid & 31, cs = tid >> 5;
    const float* xp = x + (size_t)b * NC * NSEQ + (size_t)cs * 64 * NSEQ + pg + px;
    float s = 0.f, s2 = 0.f;
#pragma unroll 8
    for (int c = 0; c < 64; c++) {
        float v = __ldg(xp + (size_t)c * NSEQ);
        s += v; s2 += v * v;
    }
    ssum[cs][px] = s; ssq[cs][px] = s2;
    __syncthreads();
    if (tid < 32) {
        float S = 0.f, S2 = 0.f;
#pragma unroll
        for (int i = 0; i < 8; i++) { S += ssum[i][tid]; S2 += ssq[i][tid]; }
        float mn  = S * (1.f / NC);
        float var = fmaxf(S2 * (1.f / NC) - mn * mn, 0.f);
        smn[tid] = mn;
        srs[tid] = rsqrtf(var + 1e-5f);
    }
    __syncthreads();
    float mn = smn[px], rs = srs[px];
    __half* xo = xn + (size_t)b * NC * NSEQ + (size_t)cs * 64 * NSEQ + pg + px;
#pragma unroll 4
    for (int c = 0; c < 64; c++) {
        float v = __ldg(xp + (size_t)c * NSEQ);
        float sc = __ldg(&scale[cs * 64 + c]);
        xo[(size_t)c * NSEQ] = __float2half((v - mn) * rs * sc);
    }
}

// ---------------- 2/5) all-fp16 GEMM, cp.async double-buffered (proven) ----------------
#define WPAD 40

template <typename Tout>
__global__ __launch_bounds__(256, 2) void gemm_f16(const __half* __restrict__ Wg,
                                                   const __half* __restrict__ A,
                                                   Tout* __restrict__ out, int O)
{
    __shared__ __align__(16) __half Ws[2][128 * WPAD];
    __shared__ __align__(16) __half Xs[2][32 * 128];

    const int P = NSEQ;
    int b  = blockIdx.z;
    int o0 = blockIdx.y * 128, p0 = blockIdx.x * 128;
    int tid = threadIdx.x, wid = tid >> 5, lane = tid & 31;
    int gr = lane >> 2, tg = lane & 3;
    int wm = wid & 3, wn = wid >> 2;
    int nb = wn * 64;
    int frow = (lane & 7) + 8 * ((lane >> 3) & 1);
    int fch  = lane >> 4;
    uint32_t ws_b = smem_u32(&Ws[0][0]);
    uint32_t xs_b = smem_u32(&Xs[0][0]);

    const __half* Wp = Wg + (size_t)o0 * NC;
    const __half* Ap = A + (size_t)b * NC * P + p0;
    Tout* Ob = out + (size_t)b * O * P;

    float acc[2][8][4];
#pragma unroll
    for (int im = 0; im < 2; im++)
#pragma unroll
        for (int nt = 0; nt < 8; nt++)
#pragma unroll
            for (int c = 0; c < 4; c++) acc[im][nt][c] = 0.f;

    auto stage = [&](int kc, int buf) {
        int c0 = kc * 32;
#pragma unroll
        for (int it = 0; it < 2; it++) {
            int idx = tid + it * 256;
            int o = idx >> 2, kk8 = (idx & 3) << 3;
            uint32_t dst = ws_b + buf * (128 * WPAD * 2) + o * (WPAD * 2) + kk8 * 2;
            CP16(dst, Wp + (size_t)o * NC + c0 + kk8);
        }
#pragma unroll
        for (int it = 0; it < 2; it++) {
            int idx = tid + it * 256;
            int k = idx >> 4, ch = idx & 15;
            uint32_t dst = xs_b + buf * 8192 + k * 256 + ((ch ^ (k & 7)) << 4);
            CP16(dst, Ap + (size_t)(c0 + k) * P + ch * 8);
        }
    };

    stage(0, 0); CPCOMMIT();
    for (int kc = 0; kc < 16; kc++) {
        int buf = kc & 1;
        if (kc < 15) { stage(kc + 1, buf ^ 1); CPCOMMIT(); CPWAIT(1); }
        else CPWAIT(0);
        __syncthreads();

        const __half* Wsb = &Ws[buf][0];
        uint32_t xb = xs_b + buf * 8192;
#pragma unroll
        for (int s = 0; s < 2; s++) {
            uint32_t a[2][4];
#pragma unroll
            for (int im = 0; im < 2; im++) {
                int r = wm * 32 + im * 16 + gr;
                a[im][0] = *(const uint32_t*)&Wsb[r * WPAD + s * 16 + 2 * tg];
                a[im][1] = *(const uint32_t*)&Wsb[(r + 8) * WPAD + s * 16 + 2 * tg];
                a[im][2] = *(const uint32_t*)&Wsb[r * WPAD + s * 16 + 2 * tg + 8];
                a[im][3] = *(const uint32_t*)&Wsb[(r + 8) * WPAD + s * 16 + 2 * tg + 8];
            }
#pragma unroll
            for (int ntp = 0; ntp < 4; ntp++) {
                uint32_t m0, m1, m2, m3;
                uint32_t addr = xb + (s * 16 + frow) * 256 +
                                (((8 * wn + 2 * ntp + fch) ^ (frow & 7)) << 4);
                ldsm4t(m0, m1, m2, m3, addr);
                mma_f16(acc[0][2 * ntp],     a[0], m0, m1);
                mma_f16(acc[1][2 * ntp],     a[1], m0, m1);
                mma_f16(acc[0][2 * ntp + 1], a[0], m2, m3);
                mma_f16(acc[1][2 * ntp + 1], a[1], m2, m3);
            }
        }
        __syncthreads();
    }

#pragma unroll
    for (int im = 0; im < 2; im++) {
        int o = o0 + wm * 32 + im * 16 + gr;
#pragma unroll
        for (int nt = 0; nt < 8; nt++) {
            int p = p0 + nb + nt * 8 + 2 * tg;
            if constexpr (sizeof(Tout) == 4) {
                *(float2*)&Ob[(size_t)o * P + p]       = make_float2(acc[im][nt][0], acc[im][nt][1]);
                *(float2*)&Ob[(size_t)(o + 8) * P + p] = make_float2(acc[im][nt][2], acc[im][nt][3]);
            } else {
                *(half2*)&Ob[(size_t)o * P + p]       = __floats2half2_rn(acc[im][nt][0], acc[im][nt][1]);
                *(half2*)&Ob[(size_t)(o + 8) * P + p] = __floats2half2_rn(acc[im][nt][2], acc[im][nt][3]);
            }
        }
    }
}

// ---------------- 3) depthwise 3x3: padded layout, 4-pixel groups, float2 taps ----------------
// smem: [64 d][6 rows][34 x] floats, d-stride 206. LDS.64 conflict-free (14d mod 32
// distinct per half-warp phase). __launch_bounds__(256,4) -> 64-reg budget, no spills.
#define DSTRIDE 206
#define DW_SMEM (64 * DSTRIDE * 4)

__global__ __launch_bounds__(256, 4) void dwconv_kernel(const __half* __restrict__ qkv,
        const float* __restrict__ wq, const float* __restrict__ bq,
        const float* __restrict__ wk, const float* __restrict__ bk,
        const float* __restrict__ wv, const float* __restrict__ bv,
        __half* __restrict__ oq, __half* __restrict__ ok, __half* __restrict__ ov)
{
    extern __shared__ float in_s[];
    int t = blockIdx.z % 3, b = blockIdx.z / 3;
    int h = blockIdx.y, y0 = blockIdx.x * 4;
    const float* w  = (t == 0) ? wq : (t == 1) ? wk : wv;
    const float* bi = (t == 0) ? bq : (t == 1) ? bk : bv;
    __half* op      = (t == 0) ? oq : (t == 1) ? ok : ov;
    float mul = (t == 0) ? 0.125f * LOG2E : 1.0f;

    int tid = threadIdx.x;
    const __half* src = qkv + ((size_t)b * 3 * NC + t * NC + h * ND) * NSEQ;

    // stage rows y0-1..y0+4 with zero halo in x and y
    int x = tid & 31;
    for (int pr = tid >> 5; pr < 384; pr += 8) {   // pr = d*6 + ys
        int d = pr / 6, ys = pr - d * 6;
        int yy = y0 - 1 + ys;
        float val = 0.f;
        if (yy >= 0 && yy < 32) val = __half2float(src[(size_t)d * NSEQ + yy * 32 + x]);
        float* row = in_s + d * DSTRIDE + ys * 34;
        row[x + 1] = val;
        if (x == 0)  row[0]  = 0.f;
        if (x == 31) row[33] = 0.f;
    }

    int d = tid & 63, yq = tid >> 6;
    float w9[9];
#pragma unroll
    for (int j = 0; j < 9; j++) w9[j] = __ldg(&w[(h * ND + d) * 9 + j]);
    float bb = __ldg(&bi[h * ND + d]);
    __syncthreads();

    const float* rp = in_s + d * DSTRIDE + yq * 34;
    __half* outbase = op + ((size_t)(b * NH + h) * NSEQ + (y0 + yq) * 32) * ND + d;

#pragma unroll
    for (int g = 0; g < 32; g += 4) {
        float2 r0a = *(const float2*)(rp + g);
        float2 r0b = *(const float2*)(rp + g + 2);
        float2 r0c = *(const float2*)(rp + g + 4);
        float2 r1a = *(const float2*)(rp + 34 + g);
        float2 r1b = *(const float2*)(rp + 34 + g + 2);
        float2 r1c = *(const float2*)(rp + 34 + g + 4);
        float2 r2a = *(const float2*)(rp + 68 + g);
        float2 r2b = *(const float2*)(rp + 68 + g + 2);
        float2 r2c = *(const float2*)(rp + 68 + g + 4);
        float t0[6] = { r0a.x, r0a.y, r0b.x, r0b.y, r0c.x, r0c.y };
        float t1[6] = { r1a.x, r1a.y, r1b.x, r1b.y, r1c.x, r1c.y };
        float t2[6] = { r2a.x, r2a.y, r2b.x, r2b.y, r2c.x, r2c.y };
#pragma unroll
        for (int p = 0; p < 4; p++) {
            float acc = bb
                + t0[p] * w9[0] + t0[p + 1] * w9[1] + t0[p + 2] * w9[2]
                + t1[p] * w9[3] + t1[p + 1] * w9[4] + t1[p + 2] * w9[5]
                + t2[p] * w9[6] + t2[p + 1] * w9[7] + t2[p + 2] * w9[8];
            outbase[(size_t)(g + p) * ND] = __float2half(acc * mul);
        }
    }
}

// ---------------- 4) flash attention: fp16 + ldmatrix + coalesced epilogue (proven) ----------------
#define QS_B 0
#define KS_B 16384
#define VS_B 24576
#define PS_B 32768
#define BS_B 49152
#define BSTRIDE 328
#define FL_SMEM (49152 + 4 * BSTRIDE * 4)
#define OT_STRIDE 272

__global__ __launch_bounds__(256, 2) void flash_mma(const __half* __restrict__ q,
                                                    const __half* __restrict__ k,
                                                    const __half* __restrict__ v,
                                                    const float* __restrict__ pos_bias,
                                                    __half* __restrict__ att)
{
    extern __shared__ char smc[];
    uint32_t sb = smem_u32(smc);
    float* Bsf = (float*)(smc + BS_B);

    int tid = threadIdx.x, wid = tid >> 5, lane = tid & 31;
    int gr = lane >> 2, tg = lane & 3;
    int qt = blockIdx.x, bh = blockIdx.y;
    int h = bh & 7, b = bh >> 3;
    size_t base = (size_t)bh * NSEQ * ND;

    int r0l = wid * 16 + gr, r1l = r0l + 8;
    int frow = (lane & 7) + 8 * ((lane >> 3) & 1);
    int fch  = lane >> 4;
    const float* Bw = Bsf + tg * BSTRIDE;

    {
        const __half* qg = q + base + (size_t)qt * 128 * ND;
#pragma unroll
        for (int p = 0; p < 4; p++) {
            int row = wid * 16 + (lane & 7) + 8 * (p & 1);
            int ch  = (lane >> 3) + 4 * (p >> 1);
            uint4 t4 = *(const uint4*)(qg + (size_t)row * ND + ch * 8);
            *(uint4*)(smc + QS_B + row * 128 + ((ch ^ (lane & 7)) << 4)) = t4;
        }
    }
    __syncthreads();

    uint32_t qa[4][4];
#pragma unroll
    for (int c = 0; c < 4; c++) {
        uint32_t addr = sb + QS_B + (wid * 16 + frow) * 128 + (((2 * c + fch) ^ (frow & 7)) << 4);
        ldsm4(qa[c][0], qa[c][1], qa[c][2], qa[c][3], addr);
    }

    float accO[8][4];
#pragma unroll
    for (int n = 0; n < 8; n++)
#pragma unroll
        for (int c = 0; c < 4; c++) accO[n][c] = 0.f;
    float lsum0 = 0.f, lsum1 = 0.f;

    int xi0 = r0l & 31, yi0 = r0l >> 5;
    int xi1 = r1l & 31, yi1 = r1l >> 5;

    for (int kt = 0; kt < 16; kt++) {
        __syncthreads();
        {
            const __half* kg = k + base + (size_t)kt * 64 * ND;
            const __half* vg = v + base + (size_t)kt * 64 * ND;
            int row = wid * 8 + (lane & 7);
#pragma unroll
            for (int p = 0; p < 2; p++) {
                int ch = (lane >> 3) + 4 * p;
                uint4 tk = *(const uint4*)(kg + (size_t)row * ND + ch * 8);
                uint4 tv = *(const uint4*)(vg + (size_t)row * ND + ch * 8);
                *(uint4*)(smc + KS_B + row * 128 + ((ch ^ (lane & 7)) << 4)) = tk;
                *(uint4*)(smc + VS_B + row * 128 + ((ch ^ (lane & 7)) << 4)) = tv;
            }
            int rel0 = qt * 4 - kt * 2 - 1;
            if (tid < 315) {
                int ry = tid / 63, rx = tid - ry * 63;
                float bv0 = __ldg(&pos_bias[((rel0 + ry + 31) * 63 + rx) * NH + h]) * LOG2E;
#pragma unroll
                for (int cp = 0; cp < 4; cp++) Bsf[cp * BSTRIDE + tid] = bv0;
            }
            if (tid + 256 < 315) {
                int i2 = tid + 256, ry = i2 / 63, rx = i2 - ry * 63;
                float bv1 = __ldg(&pos_bias[((rel0 + ry + 31) * 63 + rx) * NH + h]) * LOG2E;
#pragma unroll
                for (int cp = 0; cp < 4; cp++) Bsf[cp * BSTRIDE + i2] = bv1;
            }
        }
        __syncthreads();

        float fS[8][4];
#pragma unroll
        for (int n = 0; n < 8; n++)
#pragma unroll
            for (int c = 0; c < 4; c++) fS[n][c] = 0.f;
#pragma unroll
        for (int c = 0; c < 4; c++) {
#pragma unroll
            for (int ntp = 0; ntp < 4; ntp++) {
                uint32_t m0, m1, m2, m3;
                uint32_t addr = sb + KS_B + (ntp * 16 + frow) * 128 +
                                (((2 * c + fch) ^ (frow & 7)) << 4);
                ldsm4(m0, m1, m2, m3, addr);
                mma_f16(fS[2 * ntp],     qa[c], m0, m2);
                mma_f16(fS[2 * ntp + 1], qa[c], m1, m3);
            }
        }

#pragma unroll
        for (int nt = 0; nt < 8; nt++) {
#pragma unroll
            for (int c2 = 0; c2 < 2; c2++) {
                int jl = nt * 8 + 2 * tg + c2;
                int yj = jl >> 5, xj = jl & 31;
                float e0 = ex2(fS[nt][c2] + Bw[(yi0 - yj + 1) * 63 + xi0 - xj + 31]);
                lsum0 += e0;
                fS[nt][c2] = e0;
                float e1 = ex2(fS[nt][2 + c2] + Bw[(yi1 - yj + 1) * 63 + xi1 - xj + 31]);
                lsum1 += e1;
                fS[nt][2 + c2] = e1;
            }
            *(half2*)(smc + PS_B + r0l * 128 + ((nt ^ gr) << 4) + 4 * tg) =
                __floats2half2_rn(fS[nt][0], fS[nt][1]);
            *(half2*)(smc + PS_B + r1l * 128 + ((nt ^ gr) << 4) + 4 * tg) =
                __floats2half2_rn(fS[nt][2], fS[nt][3]);
        }
        __syncwarp();

#pragma unroll
        for (int c = 0; c < 4; c++) {
            uint32_t pa[4];
            uint32_t paddr = sb + PS_B + (wid * 16 + frow) * 128 +
                             (((2 * c + fch) ^ (frow & 7)) << 4);
            ldsm4(pa[0], pa[1], pa[2], pa[3], paddr);
#pragma unroll
            for (int ntp = 0; ntp < 4; ntp++) {
                uint32_t m0, m1, m2, m3;
                uint32_t vaddr = sb + VS_B + (c * 16 + frow) * 128 +
                                 (((2 * ntp + fch) ^ (frow & 7)) << 4);
                ldsm4t(m0, m1, m2, m3, vaddr);
                mma_f16(accO[2 * ntp],     pa, m0, m1);
                mma_f16(accO[2 * ntp + 1], pa, m2, m3);
            }
        }
    }

    lsum0 += __shfl_xor_sync(0xffffffffu, lsum0, 1);
    lsum0 += __shfl_xor_sync(0xffffffffu, lsum0, 2);
    lsum1 += __shfl_xor_sync(0xffffffffu, lsum1, 1);
    lsum1 += __shfl_xor_sync(0xffffffffu, lsum1, 2);
    float inv0 = 1.f / lsum0, inv1 = 1.f / lsum1;

    __syncthreads();
#pragma unroll
    for (int nt = 0; nt < 8; nt++) {
        int dv0 = nt * 8 + 2 * tg;
        *(__half*)(smc + dv0 * OT_STRIDE + r0l * 2)       = __float2half(accO[nt][0] * inv0);
        *(__half*)(smc + (dv0 + 1) * OT_STRIDE + r0l * 2) = __float2half(accO[nt][1] * inv0);
        *(__half*)(smc + dv0 * OT_STRIDE + r1l * 2)       = __float2half(accO[nt][2] * inv1);
        *(__half*)(smc + (dv0 + 1) * OT_STRIDE + r1l * 2) = __float2half(accO[nt][3] * inv1);
    }
    __syncthreads();
    {
        __half* ab = att + ((size_t)b * NC + h * ND) * NSEQ + (size_t)qt * 128;
#pragma unroll
        for (int it = 0; it < 4; it++) {
            int cid = tid + it * 256;
            int dv = cid >> 4, ic = cid & 15;
            uint4 t4 = *(const uint4*)(smc + dv * OT_STRIDE + ic * 16);
            *(uint4*)(ab + (size_t)dv * NSEQ + ic * 8) = t4;
        }
    }
}

// ---------------- launch ----------------
extern "C" void kernel_launch(void* const* d_in, const int* in_sizes, int n_in,
                              void* d_out, int out_size)
{
    const float* x        = (const float*)d_in[0];
    const float* scale    = (const float*)d_in[1];
    const float* w_qkv    = (const float*)d_in[2];
    const float* dw_w_q   = (const float*)d_in[3];
    const float* dw_b_q   = (const float*)d_in[4];
    const float* dw_w_k   = (const float*)d_in[5];
    const float* dw_b_k   = (const float*)d_in[6];
    const float* dw_w_v   = (const float*)d_in[7];
    const float* dw_b_v   = (const float*)d_in[8];
    const float* w_out    = (const float*)d_in[9];
    const float* pos_bias = (const float*)d_in[10];
    float* out = (float*)d_out;

    __half *xn, *w16qkv, *w16out, *qkv, *qb, *kb, *vb, *attb;
    cudaGetSymbolAddress((void**)&xn,     g_xn);
    cudaGetSymbolAddress((void**)&w16qkv, g_w16qkv);
    cudaGetSymbolAddress((void**)&w16out, g_w16out);
    cudaGetSymbolAddress((void**)&qkv,    g_qkv);
    cudaGetSymbolAddress((void**)&qb,     g_q);
    cudaGetSymbolAddress((void**)&kb,     g_k);
    cudaGetSymbolAddress((void**)&vb,     g_v);
    cudaGetSymbolAddress((void**)&attb,   g_att);

    cudaFuncSetAttribute(dwconv_kernel, cudaFuncAttributeMaxDynamicSharedMemorySize, DW_SMEM);
    cudaFuncSetAttribute(flash_mma,     cudaFuncAttributeMaxDynamicSharedMemorySize, FL_SMEM);

    wconv_kernel<<<(3 * NC * NC + NC * NC) / 4 / 256, 256>>>(w_qkv, w_out, w16qkv, w16out);
    stats_norm_kernel<<<512, 256>>>(x, scale, xn);
    gemm_f16<__half><<<dim3(8, 12, 16), 256>>>(w16qkv, xn, qkv, 3 * NC);
    dwconv_kernel<<<dim3(8, 8, 48), 256, DW_SMEM>>>(qkv, dw_w_q, dw_b_q, dw_w_k, dw_b_k,
                                                    dw_w_v, dw_b_v, qb, kb, vb);
    flash_mma<<<dim3(8, 128), 256, FL_SMEM>>>(qb, kb, vb, pos_bias, attb);
    gemm_f16<float><<<dim3(8, 4, 16), 256>>>(w16out, attb, out, NC);
}

// round 15
// speedup vs baseline: 1.2970x; 1.2970x over previous
#include <cuda_runtime.h>
#include <cuda_fp16.h>
#include <stdint.h>

#define NB 16
#define NC 512
#define NS 32
#define NH 8
#define ND 64
#define NSEQ 1024
#define LOG2E 1.44269504f

// ---------------- scratch ----------------
__device__ __align__(16) __half g_xn[(size_t)NB * NC * NSEQ];       // LN-normalized x, fp16
__device__ __align__(16) __half g_w16qkv[3 * NC * NC];              // fp16 weights
__device__ __align__(16) __half g_w16out[NC * NC];
__device__ __align__(16) __half g_qkv[(size_t)NB * 3 * NC * NSEQ];  // [B,1536,1024] fp16
__device__ __align__(16) __half g_q[(size_t)NB * NH * NSEQ * ND];   // [bh,seq,d] fp16
__device__ __align__(16) __half g_k[(size_t)NB * NH * NSEQ * ND];
__device__ __align__(16) __half g_v[(size_t)NB * NH * NSEQ * ND];
__device__ __align__(16) __half g_att[(size_t)NB * NC * NSEQ];      // [B,512,1024] fp16

__device__ __forceinline__ float ex2(float x) {
    float r; asm("ex2.approx.ftz.f32 %0, %1;" : "=f"(r) : "f"(x)); return r;
}
__device__ __forceinline__ uint32_t smem_u32(const void* p) {
    uint32_t a;
    asm("{ .reg .u64 t; cvta.to.shared.u64 t, %1; cvt.u32.u64 %0, t; }" : "=r"(a) : "l"(p));
    return a;
}
__device__ __forceinline__ void mma_f16(float* c, const uint32_t* a, uint32_t b0, uint32_t b1) {
    asm volatile(
        "mma.sync.aligned.m16n8k16.row.col.f32.f16.f16.f32 "
        "{%0,%1,%2,%3}, {%4,%5,%6,%7}, {%8,%9}, {%0,%1,%2,%3};"
        : "+f"(c[0]), "+f"(c[1]), "+f"(c[2]), "+f"(c[3])
        : "r"(a[0]), "r"(a[1]), "r"(a[2]), "r"(a[3]), "r"(b0), "r"(b1));
}
__device__ __forceinline__ void ldsm4(uint32_t& r0, uint32_t& r1, uint32_t& r2, uint32_t& r3,
                                      uint32_t addr) {
    asm volatile("ldmatrix.sync.aligned.m8n8.x4.shared.b16 {%0,%1,%2,%3}, [%4];"
                 : "=r"(r0), "=r"(r1), "=r"(r2), "=r"(r3) : "r"(addr));
}
__device__ __forceinline__ void ldsm4t(uint32_t& r0, uint32_t& r1, uint32_t& r2, uint32_t& r3,
                                       uint32_t addr) {
    asm volatile("ldmatrix.sync.aligned.m8n8.x4.trans.shared.b16 {%0,%1,%2,%3}, [%4];"
                 : "=r"(r0), "=r"(r1), "=r"(r2), "=r"(r3) : "r"(addr));
}
#define CP16(dst, src) asm volatile("cp.async.cg.shared.global [%0], [%1], 16;" :: "r"(dst), "l"(src))
#define CPCOMMIT() asm volatile("cp.async.commit_group;" ::)
#define CPWAIT(n) asm volatile("cp.async.wait_group %0;" :: "n"(n))

// ---------------- 0) weight fp32 -> fp16 ----------------
__global__ __launch_bounds__(256) void wconv_kernel(const float* __restrict__ wq,
                                                    const float* __restrict__ wo,
                                                    __half* __restrict__ hq,
                                                    __half* __restrict__ ho)
{
    int idx = blockIdx.x * 256 + threadIdx.x;
    const int n1 = 3 * NC * NC / 4;
    if (idx < n1) {
        float4 v = *(const float4*)(wq + (size_t)idx * 4);
        *(half2*)(hq + (size_t)idx * 4)     = __floats2half2_rn(v.x, v.y);
        *(half2*)(hq + (size_t)idx * 4 + 2) = __floats2half2_rn(v.z, v.w);
    } else {
        int j = idx - n1;
        float4 v = *(const float4*)(wo + (size_t)j * 4);
        *(half2*)(ho + (size_t)j * 4)     = __floats2half2_rn(v.x, v.y);
        *(half2*)(ho + (size_t)j * 4 + 2) = __floats2half2_rn(v.z, v.w);
    }
}

// ---------------- 1) fused stats + LN-normalize -> fp16 xn ----------------
__global__ __launch_bounds__(256) void stats_norm_kernel(const float* __restrict__ x,
                                                         const float* __restrict__ scale,
                                                         __half* __restrict__ xn)
{
    __shared__ float ssum[8][33], ssq[8][33];
    __shared__ float smn[32], srs[32];
    int bid = blockIdx.x;
    int b = bid >> 5, pg = (bid & 31) * 32;
    int tid = threadIdx.x;
    int px = tid & 31, cs = tid >> 5;
    const float* xp = x + (size_t)b * NC * NSEQ + (size_t)cs * 64 * NSEQ + pg + px;
    float s = 0.f, s2 = 0.f;
#pragma unroll 8
    for (int c = 0; c < 64; c++) {
        float v = __ldg(xp + (size_t)c * NSEQ);
        s += v; s2 += v * v;
    }
    ssum[cs][px] = s; ssq[cs][px] = s2;
    __syncthreads();
    if (tid < 32) {
        float S = 0.f, S2 = 0.f;
#pragma unroll
        for (int i = 0; i < 8; i++) { S += ssum[i][tid]; S2 += ssq[i][tid]; }
        float mn  = S * (1.f / NC);
        float var = fmaxf(S2 * (1.f / NC) - mn * mn, 0.f);
        smn[tid] = mn;
        srs[tid] = rsqrtf(var + 1e-5f);
    }
    __syncthreads();
    float mn = smn[px], rs = srs[px];
    __half* xo = xn + (size_t)b * NC * NSEQ + (size_t)cs * 64 * NSEQ + pg + px;
#pragma unroll 4
    for (int c = 0; c < 64; c++) {
        float v = __ldg(xp + (size_t)c * NSEQ);
        float sc = __ldg(&scale[cs * 64 + c]);
        xo[(size_t)c * NSEQ] = __float2half((v - mn) * rs * sc);
    }
}

// ---------------- 2/5) all-fp16 GEMM, cp.async double-buffered (proven) ----------------
#define WPAD 40

template <typename Tout>
__global__ __launch_bounds__(256, 2) void gemm_f16(const __half* __restrict__ Wg,
                                                   const __half* __restrict__ A,
                                                   Tout* __restrict__ out, int O)
{
    __shared__ __align__(16) __half Ws[2][128 * WPAD];
    __shared__ __align__(16) __half Xs[2][32 * 128];

    const int P = NSEQ;
    int b  = blockIdx.z;
    int o0 = blockIdx.y * 128, p0 = blockIdx.x * 128;
    int tid = threadIdx.x, wid = tid >> 5, lane = tid & 31;
    int gr = lane >> 2, tg = lane & 3;
    int wm = wid & 3, wn = wid >> 2;
    int nb = wn * 64;
    int frow = (lane & 7) + 8 * ((lane >> 3) & 1);
    int fch  = lane >> 4;
    uint32_t ws_b = smem_u32(&Ws[0][0]);
    uint32_t xs_b = smem_u32(&Xs[0][0]);

    const __half* Wp = Wg + (size_t)o0 * NC;
    const __half* Ap = A + (size_t)b * NC * P + p0;
    Tout* Ob = out + (size_t)b * O * P;

    float acc[2][8][4];
#pragma unroll
    for (int im = 0; im < 2; im++)
#pragma unroll
        for (int nt = 0; nt < 8; nt++)
#pragma unroll
            for (int c = 0; c < 4; c++) acc[im][nt][c] = 0.f;

    auto stage = [&](int kc, int buf) {
        int c0 = kc * 32;
#pragma unroll
        for (int it = 0; it < 2; it++) {
            int idx = tid + it * 256;
            int o = idx >> 2, kk8 = (idx & 3) << 3;
            uint32_t dst = ws_b + buf * (128 * WPAD * 2) + o * (WPAD * 2) + kk8 * 2;
            CP16(dst, Wp + (size_t)o * NC + c0 + kk8);
        }
#pragma unroll
        for (int it = 0; it < 2; it++) {
            int idx = tid + it * 256;
            int k = idx >> 4, ch = idx & 15;
            uint32_t dst = xs_b + buf * 8192 + k * 256 + ((ch ^ (k & 7)) << 4);
            CP16(dst, Ap + (size_t)(c0 + k) * P + ch * 8);
        }
    };

    stage(0, 0); CPCOMMIT();
    for (int kc = 0; kc < 16; kc++) {
        int buf = kc & 1;
        if (kc < 15) { stage(kc + 1, buf ^ 1); CPCOMMIT(); CPWAIT(1); }
        else CPWAIT(0);
        __syncthreads();

        const __half* Wsb = &Ws[buf][0];
        uint32_t xb = xs_b + buf * 8192;
#pragma unroll
        for (int s = 0; s < 2; s++) {
            uint32_t a[2][4];
#pragma unroll
            for (int im = 0; im < 2; im++) {
                int r = wm * 32 + im * 16 + gr;
                a[im][0] = *(const uint32_t*)&Wsb[r * WPAD + s * 16 + 2 * tg];
                a[im][1] = *(const uint32_t*)&Wsb[(r + 8) * WPAD + s * 16 + 2 * tg];
                a[im][2] = *(const uint32_t*)&Wsb[r * WPAD + s * 16 + 2 * tg + 8];
                a[im][3] = *(const uint32_t*)&Wsb[(r + 8) * WPAD + s * 16 + 2 * tg + 8];
            }
#pragma unroll
            for (int ntp = 0; ntp < 4; ntp++) {
                uint32_t m0, m1, m2, m3;
                uint32_t addr = xb + (s * 16 + frow) * 256 +
                                (((8 * wn + 2 * ntp + fch) ^ (frow & 7)) << 4);
                ldsm4t(m0, m1, m2, m3, addr);
                mma_f16(acc[0][2 * ntp],     a[0], m0, m1);
                mma_f16(acc[1][2 * ntp],     a[1], m0, m1);
                mma_f16(acc[0][2 * ntp + 1], a[0], m2, m3);
                mma_f16(acc[1][2 * ntp + 1], a[1], m2, m3);
            }
        }
        __syncthreads();
    }

#pragma unroll
    for (int im = 0; im < 2; im++) {
        int o = o0 + wm * 32 + im * 16 + gr;
#pragma unroll
        for (int nt = 0; nt < 8; nt++) {
            int p = p0 + nb + nt * 8 + 2 * tg;
            if constexpr (sizeof(Tout) == 4) {
                *(float2*)&Ob[(size_t)o * P + p]       = make_float2(acc[im][nt][0], acc[im][nt][1]);
                *(float2*)&Ob[(size_t)(o + 8) * P + p] = make_float2(acc[im][nt][2], acc[im][nt][3]);
            } else {
                *(half2*)&Ob[(size_t)o * P + p]       = __floats2half2_rn(acc[im][nt][0], acc[im][nt][1]);
                *(half2*)&Ob[(size_t)(o + 8) * P + p] = __floats2half2_rn(acc[im][nt][2], acc[im][nt][3]);
            }
        }
    }
}

// ---------------- 3) depthwise 3x3 (round-11 version, 109us proven) ----------------
#define DW_SMEM (6 * 32 * 65 * 4)

__global__ __launch_bounds__(256) void dwconv_kernel(const __half* __restrict__ qkv,
        const float* __restrict__ wq, const float* __restrict__ bq,
        const float* __restrict__ wk, const float* __restrict__ bk,
        const float* __restrict__ wv, const float* __restrict__ bv,
        __half* __restrict__ oq, __half* __restrict__ ok, __half* __restrict__ ov)
{
    extern __shared__ float in_s[];   // [6*32][65]
    int t = blockIdx.z % 3, b = blockIdx.z / 3;
    int h = blockIdx.y, y0 = blockIdx.x * 4;
    const float* w  = (t == 0) ? wq : (t == 1) ? wk : wv;
    const float* bi = (t == 0) ? bq : (t == 1) ? bk : bv;
    __half* op      = (t == 0) ? oq : (t == 1) ? ok : ov;
    float mul = (t == 0) ? 0.125f * LOG2E : 1.0f;

    int tid = threadIdx.x;
    const __half* src = qkv + ((size_t)b * 3 * NC + t * NC + h * ND) * NSEQ;

    int x = tid & 31;
    for (int pr = tid >> 5; pr < 384; pr += 8) {
        int d = pr / 6, ys = pr - d * 6;
        int yy = y0 - 1 + ys;
        float val = 0.f;
        if (yy >= 0 && yy < 32) val = __half2float(src[(size_t)d * NSEQ + yy * 32 + x]);
        in_s[(ys * 32 + x) * 65 + d] = val;
    }

    int d = tid & 63, yq = tid >> 6;
    float w9[9];
#pragma unroll
    for (int j = 0; j < 9; j++) w9[j] = __ldg(&w[(h * ND + d) * 9 + j]);
    float bb = __ldg(&bi[h * ND + d]);
    __syncthreads();

    __half* outbase = op + ((size_t)(b * NH + h) * NSEQ + (y0 + yq) * 32) * ND + d;
#pragma unroll 4
    for (int xo = 0; xo < 32; xo++) {
        float acc = bb;
#pragma unroll
        for (int dy = 0; dy < 3; dy++) {
            int rowoff = (yq + dy) * 32;
#pragma unroll
            for (int dx = 0; dx < 3; dx++) {
                int xx = xo + dx - 1;
                if (xx >= 0 && xx < 32)
                    acc += in_s[(rowoff + xx) * 65 + d] * w9[dy * 3 + dx];
            }
        }
        outbase[(size_t)xo * ND] = __float2half(acc * mul);
    }
}

// ---------------- 4) flash attention: cp.async double-buffered K/V ----------------
// byte layout: KS[2x8192] | VS[2x8192] | QS/PS alias [16384] | Bs [4*328 floats]
#define KS_B 0
#define VS_B 16384
#define QS_B 32768
#define PS_B 32768
#define BS_B 49152
#define BSTRIDE 328
#define FL_SMEM (49152 + 4 * BSTRIDE * 4)
#define OT_STRIDE 272

__global__ __launch_bounds__(256, 2) void flash_mma(const __half* __restrict__ q,
                                                    const __half* __restrict__ k,
                                                    const __half* __restrict__ v,
                                                    const float* __restrict__ pos_bias,
                                                    __half* __restrict__ att)
{
    extern __shared__ char smc[];
    uint32_t sb = smem_u32(smc);
    float* Bsf = (float*)(smc + BS_B);

    int tid = threadIdx.x, wid = tid >> 5, lane = tid & 31;
    int gr = lane >> 2, tg = lane & 3;
    int qt = blockIdx.x, bh = blockIdx.y;
    int h = bh & 7, b = bh >> 3;
    size_t base = (size_t)bh * NSEQ * ND;

    int r0l = wid * 16 + gr, r1l = r0l + 8;
    int frow = (lane & 7) + 8 * ((lane >> 3) & 1);
    int fch  = lane >> 4;
    const float* Bw = Bsf + tg * BSTRIDE;

    // staging coordinates for K/V cp.async
    int srow = wid * 8 + (lane & 7);
    int sxor = (lane & 7) << 4;

    // ---- stage Q tile (swizzled row-major) into QS, hoist a-fragments ----
    {
        const __half* qg = q + base + (size_t)qt * 128 * ND;
#pragma unroll
        for (int p = 0; p < 4; p++) {
            int row = wid * 16 + (lane & 7) + 8 * (p & 1);
            int ch  = (lane >> 3) + 4 * (p >> 1);
            uint4 t4 = *(const uint4*)(qg + (size_t)row * ND + ch * 8);
            *(uint4*)(smc + QS_B + row * 128 + ((ch ^ (lane & 7)) << 4)) = t4;
        }
    }
    __syncthreads();
    uint32_t qa[4][4];
#pragma unroll
    for (int c = 0; c < 4; c++) {
        uint32_t addr = sb + QS_B + (wid * 16 + frow) * 128 + (((2 * c + fch) ^ (frow & 7)) << 4);
        ldsm4(qa[c][0], qa[c][1], qa[c][2], qa[c][3], addr);
    }

    auto stageKV = [&](int kt, int buf) {
        const __half* kg = k + base + (size_t)kt * 64 * ND + (size_t)srow * ND;
        const __half* vg = v + base + (size_t)kt * 64 * ND + (size_t)srow * ND;
#pragma unroll
        for (int p = 0; p < 2; p++) {
            int ch = (lane >> 3) + 4 * p;
            uint32_t off = srow * 128 + ((ch << 4) ^ sxor);
            CP16(sb + KS_B + buf * 8192 + off, kg + ch * 8);
            CP16(sb + VS_B + buf * 8192 + off, vg + ch * 8);
        }
    };

    float accO[8][4];
#pragma unroll
    for (int n = 0; n < 8; n++)
#pragma unroll
        for (int c = 0; c < 4; c++) accO[n][c] = 0.f;
    float lsum0 = 0.f, lsum1 = 0.f;

    int xi0 = r0l & 31, yi0 = r0l >> 5;
    int xi1 = r1l & 31, yi1 = r1l >> 5;

    stageKV(0, 0); CPCOMMIT();

    for (int kt = 0; kt < 16; kt++) {
        int buf = kt & 1;
        __syncthreads();   // Bs consumed by previous iter (and qa hoist on iter 0)
        {
            int rel0 = qt * 4 - kt * 2 - 1;
            if (tid < 315) {
                int ry = tid / 63, rx = tid - ry * 63;
                float bv0 = __ldg(&pos_bias[((rel0 + ry + 31) * 63 + rx) * NH + h]) * LOG2E;
#pragma unroll
                for (int cp = 0; cp < 4; cp++) Bsf[cp * BSTRIDE + tid] = bv0;
            }
            if (tid + 256 < 315) {
                int i2 = tid + 256, ry = i2 / 63, rx = i2 - ry * 63;
                float bv1 = __ldg(&pos_bias[((rel0 + ry + 31) * 63 + rx) * NH + h]) * LOG2E;
#pragma unroll
                for (int cp = 0; cp < 4; cp++) Bsf[cp * BSTRIDE + i2] = bv1;
            }
        }
        if (kt < 15) { stageKV(kt + 1, buf ^ 1); CPCOMMIT(); CPWAIT(1); }
        else CPWAIT(0);
        __syncthreads();

        // ---- S = Q K^T ----
        float fS[8][4];
#pragma unroll
        for (int n = 0; n < 8; n++)
#pragma unroll
            for (int c = 0; c < 4; c++) fS[n][c] = 0.f;
#pragma unroll
        for (int c = 0; c < 4; c++) {
#pragma unroll
            for (int ntp = 0; ntp < 4; ntp++) {
                uint32_t m0, m1, m2, m3;
                uint32_t addr = sb + KS_B + buf * 8192 + (ntp * 16 + frow) * 128 +
                                (((2 * c + fch) ^ (frow & 7)) << 4);
                ldsm4(m0, m1, m2, m3, addr);
                mma_f16(fS[2 * ntp],     qa[c], m0, m2);
                mma_f16(fS[2 * ntp + 1], qa[c], m1, m3);
            }
        }

        // ---- softmax + P store ----
#pragma unroll
        for (int nt = 0; nt < 8; nt++) {
#pragma unroll
            for (int c2 = 0; c2 < 2; c2++) {
                int jl = nt * 8 + 2 * tg + c2;
                int yj = jl >> 5, xj = jl & 31;
                float e0 = ex2(fS[nt][c2] + Bw[(yi0 - yj + 1) * 63 + xi0 - xj + 31]);
                lsum0 += e0;
                fS[nt][c2] = e0;
                float e1 = ex2(fS[nt][2 + c2] + Bw[(yi1 - yj + 1) * 63 + xi1 - xj + 31]);
                lsum1 += e1;
                fS[nt][2 + c2] = e1;
            }
            *(half2*)(smc + PS_B + r0l * 128 + ((nt ^ gr) << 4) + 4 * tg) =
                __floats2half2_rn(fS[nt][0], fS[nt][1]);
            *(half2*)(smc + PS_B + r1l * 128 + ((nt ^ gr) << 4) + 4 * tg) =
                __floats2half2_rn(fS[nt][2], fS[nt][3]);
        }
        __syncwarp();

        // ---- O += P V ----
#pragma unroll
        for (int c = 0; c < 4; c++) {
            uint32_t pa[4];
            uint32_t paddr = sb + PS_B + (wid * 16 + frow) * 128 +
                             (((2 * c + fch) ^ (frow & 7)) << 4);
            ldsm4(pa[0], pa[1], pa[2], pa[3], paddr);
#pragma unroll
            for (int ntp = 0; ntp < 4; ntp++) {
                uint32_t m0, m1, m2, m3;
                uint32_t vaddr = sb + VS_B + buf * 8192 + (c * 16 + frow) * 128 +
                                 (((2 * ntp + fch) ^ (frow & 7)) << 4);
                ldsm4t(m0, m1, m2, m3, vaddr);
                mma_f16(accO[2 * ntp],     pa, m0, m1);
                mma_f16(accO[2 * ntp + 1], pa, m2, m3);
            }
        }
    }

    lsum0 += __shfl_xor_sync(0xffffffffu, lsum0, 1);
    lsum0 += __shfl_xor_sync(0xffffffffu, lsum0, 2);
    lsum1 += __shfl_xor_sync(0xffffffffu, lsum1, 1);
    lsum1 += __shfl_xor_sync(0xffffffffu, lsum1, 2);
    float inv0 = 1.f / lsum0, inv1 = 1.f / lsum1;

    // ---- epilogue: transpose through smem (KS/VS regions dead), coalesced STG ----
    __syncthreads();
#pragma unroll
    for (int nt = 0; nt < 8; nt++) {
        int dv0 = nt * 8 + 2 * tg;
        *(__half*)(smc + dv0 * OT_STRIDE + r0l * 2)       = __float2half(accO[nt][0] * inv0);
        *(__half*)(smc + (dv0 + 1) * OT_STRIDE + r0l * 2) = __float2half(accO[nt][1] * inv0);
        *(__half*)(smc + dv0 * OT_STRIDE + r1l * 2)       = __float2half(accO[nt][2] * inv1);
        *(__half*)(smc + (dv0 + 1) * OT_STRIDE + r1l * 2) = __float2half(accO[nt][3] * inv1);
    }
    __syncthreads();
    {
        __half* ab = att + ((size_t)b * NC + h * ND) * NSEQ + (size_t)qt * 128;
#pragma unroll
        for (int it = 0; it < 4; it++) {
            int cid = tid + it * 256;
            int dv = cid >> 4, ic = cid & 15;
            uint4 t4 = *(const uint4*)(smc + dv * OT_STRIDE + ic * 16);
            *(uint4*)(ab + (size_t)dv * NSEQ + ic * 8) = t4;
        }
    }
}

// ---------------- launch ----------------
extern "C" void kernel_launch(void* const* d_in, const int* in_sizes, int n_in,
                              void* d_out, int out_size)
{
    const float* x        = (const float*)d_in[0];
    const float* scale    = (const float*)d_in[1];
    const float* w_qkv    = (const float*)d_in[2];
    const float* dw_w_q   = (const float*)d_in[3];
    const float* dw_b_q   = (const float*)d_in[4];
    const float* dw_w_k   = (const float*)d_in[5];
    const float* dw_b_k   = (const float*)d_in[6];
    const float* dw_w_v   = (const float*)d_in[7];
    const float* dw_b_v   = (const float*)d_in[8];
    const float* w_out    = (const float*)d_in[9];
    const float* pos_bias = (const float*)d_in[10];
    float* out = (float*)d_out;

    __half *xn, *w16qkv, *w16out, *qkv, *qb, *kb, *vb, *attb;
    cudaGetSymbolAddress((void**)&xn,     g_xn);
    cudaGetSymbolAddress((void**)&w16qkv, g_w16qkv);
    cudaGetSymbolAddress((void**)&w16out, g_w16out);
    cudaGetSymbolAddress((void**)&qkv,    g_qkv);
    cudaGetSymbolAddress((void**)&qb,     g_q);
    cudaGetSymbolAddress((void**)&kb,     g_k);
    cudaGetSymbolAddress((void**)&vb,     g_v);
    cudaGetSymbolAddress((void**)&attb,   g_att);

    cudaFuncSetAttribute(dwconv_kernel, cudaFuncAttributeMaxDynamicSharedMemorySize, DW_SMEM);
    cudaFuncSetAttribute(flash_mma,     cudaFuncAttributeMaxDynamicSharedMemorySize, FL_SMEM);

    wconv_kernel<<<(3 * NC * NC + NC * NC) / 4 / 256, 256>>>(w_qkv, w_out, w16qkv, w16out);
    stats_norm_kernel<<<512, 256>>>(x, scale, xn);
    gemm_f16<__half><<<dim3(8, 12, 16), 256>>>(w16qkv, xn, qkv, 3 * NC);
    dwconv_kernel<<<dim3(8, 8, 48), 256, DW_SMEM>>>(qkv, dw_w_q, dw_b_q, dw_w_k, dw_b_k,
                                                    dw_w_v, dw_b_v, qb, kb, vb);
    flash_mma<<<dim3(8, 128), 256, FL_SMEM>>>(qb, kb, vb, pos_bias, attb);
    gemm_f16<float><<<dim3(8, 4, 16), 256>>>(w16out, attb, out, NC);
}